// round 7
// baseline (speedup 1.0000x reference)
#include <cuda_runtime.h>
#include <cuda_fp16.h>
#include <cstdint>

// Problem constants (fixed by the dataset)
#define H 128
#define TT 4095          // (8192-3)/2 + 1
#define NC 128           // scan chunks
#define LC 32            // chunk length (last chunk = 31)
#define NELEM (H * H)    // 16384 state elements
#define ZSH 136          // padded Zs row stride in halves (conflict-free)

// Scratch (allocation-free rule: __device__ globals)
static __device__ float g_Y[TT * 3 * H];   // Y[t][w][d] = (w_q @ X_t)[w,d]
static __device__ float g_S[NC * NELEM];   // chunk-local end states
static __device__ float g_cin[NC * NELEM]; // carry-in per chunk

// ---------------------------------------------------------------------------
// Kernel 1: Y[t][w][:] = sum_v wq[w][v]*x[2t+v][:], os[t][:] = sum_w D[w]*x[2t+w][:]
// ---------------------------------------------------------------------------
__global__ void prep_kernel(const float* __restrict__ in,
                            const float* __restrict__ wq,
                            const float* __restrict__ Dv,
                            float* __restrict__ os_out) {
    int t = blockIdx.x;
    int d = threadIdx.x;
    float x0 = in[(2 * t + 0) * H + d];
    float x1 = in[(2 * t + 1) * H + d];
    float x2 = in[(2 * t + 2) * H + d];
    g_Y[(t * 3 + 0) * H + d] = wq[0] * x0 + wq[1] * x1 + wq[2] * x2;
    g_Y[(t * 3 + 1) * H + d] = wq[3] * x0 + wq[4] * x1 + wq[5] * x2;
    g_Y[(t * 3 + 2) * H + d] = wq[6] * x0 + wq[7] * x1 + wq[8] * x2;
    os_out[t * H + d] = Dv[0] * x0 + Dv[1] * x1 + Dv[2] * x2;
}

// ---------------------------------------------------------------------------
// Kernel 2: chunk-local scan (zero init), batch-staged.
// ---------------------------------------------------------------------------
__global__ __launch_bounds__(256) void scan0_kernel(const float* __restrict__ in,
                                                    const float* __restrict__ Lam) {
    __shared__ float Ys[8 * 384];
    __shared__ float Xs[8 * 48];

    int c   = blockIdx.y;
    int a0  = blockIdx.x * 16;
    int tid = threadIdx.x;
    int d   = tid & 127;
    int ah  = (tid >> 7) * 8;

    float z[8], lam[8];
#pragma unroll
    for (int k = 0; k < 8; k++) {
        lam[k] = Lam[(a0 + ah + k) * H + d];
        z[k]   = 0.0f;
    }

    int t0c = c * LC;
    int t1c = t0c + LC; if (t1c > TT) t1c = TT;

    for (int tb = t0c; tb < t1c; tb += 8) {
        int nvt = t1c - tb; if (nvt > 8) nvt = 8;
        for (int i = tid; i < nvt * 384; i += 256) Ys[i] = g_Y[tb * 384 + i];
        for (int i = tid; i < nvt * 48; i += 256) {
            int tl = i / 48, r = i % 48, w = r / 16, al = r % 16;
            Xs[i] = in[(2 * (tb + tl) + w) * H + a0 + al];
        }
        __syncthreads();
        for (int tl = 0; tl < nvt; tl++) {
            float y0 = Ys[tl * 384 + d];
            float y1 = Ys[tl * 384 + 128 + d];
            float y2 = Ys[tl * 384 + 256 + d];
            const float* xs = &Xs[tl * 48 + ah];
#pragma unroll
            for (int k = 0; k < 8; k++) {
                float u = xs[k] * y0 + xs[16 + k] * y1 + xs[32 + k] * y2;
                z[k] = fmaf(lam[k], z[k], u);
            }
        }
        __syncthreads();
    }

#pragma unroll
    for (int k = 0; k < 8; k++) g_S[c * NELEM + (a0 + ah + k) * H + d] = z[k];
}

// ---------------------------------------------------------------------------
// Kernel 3: sequential carry combine across chunks.
// ---------------------------------------------------------------------------
__global__ void combine_kernel(const float* __restrict__ Lam) {
    int e = blockIdx.x * 256 + threadIdx.x;
    float lam = Lam[e];
    float p = lam;  // lam^32 via 5 squarings
    p = p * p; p = p * p; p = p * p; p = p * p; p = p * p;
    float cin = 0.0f;
    for (int c = 0; c < NC; c++) {
        g_cin[c * NELEM + e] = cin;
        cin = fmaf(p, cin, g_S[c * NELEM + e]);
    }
}

// ---------------------------------------------------------------------------
// Kernel 4: FUSED scan + GEMM, all warps both phases, double-buffered Zs,
// ONE barrier per epoch.
//   Epoch e: [bar] -> scan(e) writes Zs[e&1] -> gemm(e-1) reads Zs[(e-1)&1].
//   scan: thread owns 2a x 4d (a = a0+wrp*2+j, d = lane*4..+3); Y via LDG.128,
//         X from per-chunk smem broadcast; STS.64 fp16 stores.
//   gemm: 4(m) x 2(n) warp tiles, 32h x 64ta each; C A-frags in registers.
// ---------------------------------------------------------------------------
__global__ __launch_bounds__(256, 2) void fused_kernel(const float* __restrict__ in,
                                                       const float* __restrict__ Lam,
                                                       const float* __restrict__ Cm,
                                                       float* __restrict__ out) {
    extern __shared__ float smem[];
    __half* ZsA  = (__half*)smem;             // 128 * ZSH halves
    __half* ZsB  = ZsA + 128 * ZSH;
    float*  Xall = (float*)(ZsB + 128 * ZSH); // 67 * 16 floats (whole chunk)

    int tid = threadIdx.x;
    int c   = blockIdx.y;
    int a0  = blockIdx.x * 16;
    int wrp = tid >> 5, l = tid & 31;

    int t0c = c * LC;
    int t1c = t0c + LC; if (t1c > TT) t1c = TT;
    int nb  = (t1c - t0c + 7) >> 3;   // always 4

    // stage X for the whole chunk: rows 2*t0c .. 2*t0c+66, 16 a's
    for (int i = tid; i < 67 * 16; i += 256) {
        int r = i >> 4, al = i & 15;
        int row = 2 * t0c + r;
        Xall[i] = (row < 8192) ? in[(size_t)row * H + a0 + al] : 0.0f;
    }

    // scan state: 2 a x 4 d
    int d4 = l * 4;
    float z[8], lam[8];
#pragma unroll
    for (int j = 0; j < 2; j++) {
        int a = a0 + wrp * 2 + j;
        float4 lv = *(const float4*)&Lam[a * H + d4];
        float4 cv = *(const float4*)&g_cin[c * NELEM + a * H + d4];
        lam[j * 4 + 0] = lv.x; lam[j * 4 + 1] = lv.y;
        lam[j * 4 + 2] = lv.z; lam[j * 4 + 3] = lv.w;
        z[j * 4 + 0] = cv.x; z[j * 4 + 1] = cv.y;
        z[j * 4 + 2] = cv.z; z[j * 4 + 3] = cv.w;
    }

    // gemm mapping + A fragments (C rows [h0,h0+32), fp16)
    int grp = l >> 2, thr = l & 3;
    int mg  = wrp & 3, ng = wrp >> 2;
    int h0  = mg * 32;
    uint32_t afr[8][8];
#pragma unroll
    for (int kt = 0; kt < 8; kt++) {
        int cb = kt * 16 + 2 * thr;
#pragma unroll
        for (int mt = 0; mt < 2; mt++) {
            const float* r0 = Cm + (h0 + mt * 16 + grp) * H;
            const float* r1 = Cm + (h0 + mt * 16 + grp + 8) * H;
            __half2 p0 = __floats2half2_rn(r0[cb],     r0[cb + 1]);
            __half2 p1 = __floats2half2_rn(r1[cb],     r1[cb + 1]);
            __half2 p2 = __floats2half2_rn(r0[cb + 8], r0[cb + 9]);
            __half2 p3 = __floats2half2_rn(r1[cb + 8], r1[cb + 9]);
            afr[kt][mt * 4 + 0] = *(uint32_t*)&p0;
            afr[kt][mt * 4 + 1] = *(uint32_t*)&p1;
            afr[kt][mt * 4 + 2] = *(uint32_t*)&p2;
            afr[kt][mt * 4 + 3] = *(uint32_t*)&p3;
        }
    }

    for (int e = 0; e <= nb; e++) {
        __syncthreads();

        // ---- scan epoch e -> Zs[e&1] ----
        if (e < nb) {
            int tb  = t0c + e * 8;
            int nvt = t1c - tb; if (nvt > 8) nvt = 8;
            __half* Zb = (e & 1) ? ZsB : ZsA;
#pragma unroll
            for (int tl = 0; tl < 8; tl++) {
                if (tl >= nvt) break;
                int t = tb + tl;
                const float* yb = g_Y + t * 384;
                float4 y0 = *(const float4*)(yb + d4);
                float4 y1 = *(const float4*)(yb + 128 + d4);
                float4 y2 = *(const float4*)(yb + 256 + d4);
                const float* xr = Xall + (size_t)(2 * (t - t0c)) * 16 + wrp * 2;
#pragma unroll
                for (int j = 0; j < 2; j++) {
                    float xa = xr[j];
                    float xm = xr[16 + j];
                    float xc = xr[32 + j];
                    float u0 = xa * y0.x + xm * y1.x + xc * y2.x;
                    float u1 = xa * y0.y + xm * y1.y + xc * y2.y;
                    float u2 = xa * y0.z + xm * y1.z + xc * y2.z;
                    float u3 = xa * y0.w + xm * y1.w + xc * y2.w;
                    z[j * 4 + 0] = fmaf(lam[j * 4 + 0], z[j * 4 + 0], u0);
                    z[j * 4 + 1] = fmaf(lam[j * 4 + 1], z[j * 4 + 1], u1);
                    z[j * 4 + 2] = fmaf(lam[j * 4 + 2], z[j * 4 + 2], u2);
                    z[j * 4 + 3] = fmaf(lam[j * 4 + 3], z[j * 4 + 3], u3);
                    __half2 p0 = __floats2half2_rn(z[j * 4 + 0], z[j * 4 + 1]);
                    __half2 p1 = __floats2half2_rn(z[j * 4 + 2], z[j * 4 + 3]);
                    uint2 pk;
                    pk.x = *(uint32_t*)&p0;
                    pk.y = *(uint32_t*)&p1;
                    *(uint2*)&Zb[(tl * 16 + wrp * 2 + j) * ZSH + d4] = pk;
                }
            }
        }

        // ---- gemm epoch e-1 <- Zs[(e-1)&1] ----
        if (e > 0) {
            int jb = e - 1;
            int tb = t0c + jb * 8;
            __half* Zb = (jb & 1) ? ZsB : ZsA;
            for (int nt = ng * 8; nt < ng * 8 + 8; nt++) {
                int t = tb + (nt >> 1);
                if (t >= TT) break;
                float acc[8];
#pragma unroll
                for (int i = 0; i < 8; i++) acc[i] = 0.0f;
                const __half* zb = Zb + (nt * 8 + grp) * ZSH + 2 * thr;
#pragma unroll
                for (int kt = 0; kt < 8; kt++) {
                    uint32_t b0 = *(const uint32_t*)(zb + kt * 16);
                    uint32_t b1 = *(const uint32_t*)(zb + kt * 16 + 8);
                    asm volatile(
                        "mma.sync.aligned.m16n8k16.row.col.f32.f16.f16.f32 "
                        "{%0,%1,%2,%3}, {%4,%5,%6,%7}, {%8,%9}, {%0,%1,%2,%3};"
                        : "+f"(acc[0]), "+f"(acc[1]), "+f"(acc[2]), "+f"(acc[3])
                        : "r"(afr[kt][0]), "r"(afr[kt][1]), "r"(afr[kt][2]),
                          "r"(afr[kt][3]), "r"(b0), "r"(b1));
                    asm volatile(
                        "mma.sync.aligned.m16n8k16.row.col.f32.f16.f16.f32 "
                        "{%0,%1,%2,%3}, {%4,%5,%6,%7}, {%8,%9}, {%0,%1,%2,%3};"
                        : "+f"(acc[4]), "+f"(acc[5]), "+f"(acc[6]), "+f"(acc[7])
                        : "r"(afr[kt][4]), "r"(afr[kt][5]), "r"(afr[kt][6]),
                          "r"(afr[kt][7]), "r"(b0), "r"(b1));
                }
                float* ob = out + (size_t)t * NELEM + a0 + (nt & 1) * 8 + 2 * thr;
                asm volatile("st.global.cs.v2.f32 [%0], {%1,%2};"
                             :: "l"(ob + (size_t)(h0 + grp) * H),
                                "f"(acc[0]), "f"(acc[1]));
                asm volatile("st.global.cs.v2.f32 [%0], {%1,%2};"
                             :: "l"(ob + (size_t)(h0 + grp + 8) * H),
                                "f"(acc[2]), "f"(acc[3]));
                asm volatile("st.global.cs.v2.f32 [%0], {%1,%2};"
                             :: "l"(ob + (size_t)(h0 + 16 + grp) * H),
                                "f"(acc[4]), "f"(acc[5]));
                asm volatile("st.global.cs.v2.f32 [%0], {%1,%2};"
                             :: "l"(ob + (size_t)(h0 + 24 + grp) * H),
                                "f"(acc[6]), "f"(acc[7]));
            }
        }
    }
}

// ---------------------------------------------------------------------------
// Launch: prep -> scan0 -> combine -> fused(scan+GEMM)
// Output layout: zs_out (T*H*H floats) followed by os (T*H floats).
// ---------------------------------------------------------------------------
extern "C" void kernel_launch(void* const* d_in, const int* in_sizes, int n_in,
                              void* d_out, int out_size) {
    const float* in  = (const float*)d_in[0];   // input_sequence (8192,128)
    const float* lam = (const float*)d_in[1];   // Lambda_bar (128,128)
    const float* Cm  = (const float*)d_in[2];   // C_tilde (128,128)
    const float* wq  = (const float*)d_in[3];   // w_q (3,3)
    const float* Dv  = (const float*)d_in[4];   // D (3,)
    (void)in_sizes; (void)n_in; (void)out_size;

    float* out    = (float*)d_out;
    float* os_out = out + (size_t)TT * NELEM;

    // smem: double-buffered Zs (halves) + Xall
    const int fused_smem =
        2 * 128 * ZSH * (int)sizeof(__half) + 67 * 16 * (int)sizeof(float);
    cudaFuncSetAttribute(fused_kernel, cudaFuncAttributeMaxDynamicSharedMemorySize,
                         fused_smem);

    prep_kernel<<<TT, H>>>(in, wq, Dv, os_out);
    scan0_kernel<<<dim3(8, NC), 256>>>(in, lam);
    combine_kernel<<<NELEM / 256, 256>>>(lam);
    fused_kernel<<<dim3(8, NC), 256, fused_smem>>>(in, lam, Cm, out);
}

// round 8
// speedup vs baseline: 1.0492x; 1.0492x over previous
#include <cuda_runtime.h>
#include <cuda_fp16.h>
#include <cstdint>

// Problem constants (fixed by the dataset)
#define H 128
#define TT 4095          // (8192-3)/2 + 1
#define NC 128           // scan chunks
#define LC 32            // chunk length (last chunk = 31)
#define NELEM (H * H)    // 16384 state elements
#define ZSH 136          // padded Zs row stride in halves (conflict-free)

// Scratch (allocation-free rule: __device__ globals)
static __device__ float g_Y[TT * 3 * H];   // Y[t][w][d] = (w_q @ X_t)[w,d]
static __device__ float g_S[NC * NELEM];   // chunk-local end states
static __device__ float g_cin[NC * NELEM]; // carry-in per chunk

static __device__ __forceinline__ uint32_t smem_u32(const void* p) {
    uint32_t a;
    asm("{ .reg .u64 t; cvta.to.shared.u64 t, %1; cvt.u32.u64 %0, t; }"
        : "=r"(a) : "l"(p));
    return a;
}

// ---------------------------------------------------------------------------
// Kernel 1: Y[t][w][:] = sum_v wq[w][v]*x[2t+v][:], os[t][:] = sum_w D[w]*x[2t+w][:]
// ---------------------------------------------------------------------------
__global__ void prep_kernel(const float* __restrict__ in,
                            const float* __restrict__ wq,
                            const float* __restrict__ Dv,
                            float* __restrict__ os_out) {
    int t = blockIdx.x;
    int d = threadIdx.x;
    float x0 = in[(2 * t + 0) * H + d];
    float x1 = in[(2 * t + 1) * H + d];
    float x2 = in[(2 * t + 2) * H + d];
    g_Y[(t * 3 + 0) * H + d] = wq[0] * x0 + wq[1] * x1 + wq[2] * x2;
    g_Y[(t * 3 + 1) * H + d] = wq[3] * x0 + wq[4] * x1 + wq[5] * x2;
    g_Y[(t * 3 + 2) * H + d] = wq[6] * x0 + wq[7] * x1 + wq[8] * x2;
    os_out[t * H + d] = Dv[0] * x0 + Dv[1] * x1 + Dv[2] * x2;
}

// ---------------------------------------------------------------------------
// Kernel 2: chunk-local scan (zero init), double-buffered Y prefetch,
// one sync per batch.
// ---------------------------------------------------------------------------
__global__ __launch_bounds__(256) void scan0_kernel(const float* __restrict__ in,
                                                    const float* __restrict__ Lam) {
    __shared__ float Ys[2][8 * 384];
    __shared__ float Xall[67 * 16];

    int c   = blockIdx.y;
    int a0  = blockIdx.x * 16;
    int tid = threadIdx.x;
    int d   = tid & 127;
    int ah  = (tid >> 7) * 8;

    int t0c = c * LC;
    int t1c = t0c + LC; if (t1c > TT) t1c = TT;
    int nb  = (t1c - t0c + 7) >> 3;   // always 4

    // prologue: prefetch Y(0); stage X for whole chunk
    {
        int nvt0 = t1c - t0c; if (nvt0 > 8) nvt0 = 8;
        uint32_t ydst = smem_u32(Ys[0]);
        const float* ysrc = g_Y + t0c * 384;
        for (int i = tid; i < nvt0 * 96; i += 256)
            asm volatile("cp.async.ca.shared.global [%0], [%1], 16;"
                         :: "r"(ydst + i * 16), "l"(ysrc + i * 4));
        asm volatile("cp.async.commit_group;");
    }
    for (int i = tid; i < 67 * 16; i += 256) {
        int r = i >> 4, al = i & 15;
        int row = 2 * t0c + r;
        Xall[i] = (row < 8192) ? in[(size_t)row * H + a0 + al] : 0.0f;
    }

    float z[8], lam[8];
#pragma unroll
    for (int k = 0; k < 8; k++) {
        lam[k] = Lam[(a0 + ah + k) * H + d];
        z[k]   = 0.0f;
    }

    for (int e = 0; e < nb; e++) {
        asm volatile("cp.async.wait_group 0;");
        __syncthreads();
        // prefetch next batch's Y
        if (e + 1 < nb) {
            int tb1  = t0c + (e + 1) * 8;
            int nvt1 = t1c - tb1; if (nvt1 > 8) nvt1 = 8;
            uint32_t ydst = smem_u32(Ys[(e + 1) & 1]);
            const float* ysrc = g_Y + tb1 * 384;
            for (int i = tid; i < nvt1 * 96; i += 256)
                asm volatile("cp.async.ca.shared.global [%0], [%1], 16;"
                             :: "r"(ydst + i * 16), "l"(ysrc + i * 4));
            asm volatile("cp.async.commit_group;");
        }
        int tb  = t0c + e * 8;
        int nvt = t1c - tb; if (nvt > 8) nvt = 8;
        const float* Yb = Ys[e & 1];
        for (int tl = 0; tl < nvt; tl++) {
            float y0 = Yb[tl * 384 + d];
            float y1 = Yb[tl * 384 + 128 + d];
            float y2 = Yb[tl * 384 + 256 + d];
            int dt = 2 * (tb - t0c + tl);
            const float* xs = &Xall[dt * 16 + ah];
#pragma unroll
            for (int k = 0; k < 8; k++) {
                float u = xs[k] * y0 + xs[16 + k] * y1 + xs[32 + k] * y2;
                z[k] = fmaf(lam[k], z[k], u);
            }
        }
    }

#pragma unroll
    for (int k = 0; k < 8; k++) g_S[c * NELEM + (a0 + ah + k) * H + d] = z[k];
}

// ---------------------------------------------------------------------------
// Kernel 3: sequential carry combine across chunks.
// ---------------------------------------------------------------------------
__global__ void combine_kernel(const float* __restrict__ Lam) {
    int e = blockIdx.x * 256 + threadIdx.x;
    float lam = Lam[e];
    float p = lam;  // lam^32 via 5 squarings
    p = p * p; p = p * p; p = p * p; p = p * p; p = p * p;
    float cin = 0.0f;
    for (int c = 0; c < NC; c++) {
        g_cin[c * NELEM + e] = cin;
        cin = fmaf(p, cin, g_S[c * NELEM + e]);
    }
}

// ---------------------------------------------------------------------------
// Kernel 4: FUSED scan + GEMM, all warps both phases, double-buffered Ys+Zs,
// ONE barrier per epoch, Y prefetch hidden under previous epoch's GEMM.
//   Epoch e: [wait+bar] -> prefetch Y(e+1) -> scan(e)->Zs[e&1]
//            -> gemm(e-1)<-Zs[(e-1)&1]
//   scan: thread owns 4a x 2d (R5 mapping); gemm: 4(m)x2(n) warp tiles,
//   C A-frags register-resident (identical numerics to R5).
// ---------------------------------------------------------------------------
__global__ __launch_bounds__(256, 2) void fused_kernel(const float* __restrict__ in,
                                                       const float* __restrict__ Lam,
                                                       const float* __restrict__ Cm,
                                                       float* __restrict__ out) {
    extern __shared__ float smem[];
    __half* ZsA  = (__half*)smem;                 // 128*ZSH halves
    __half* ZsB  = ZsA + 128 * ZSH;
    float*  YsA  = (float*)(ZsB + 128 * ZSH);     // 8*384 floats
    float*  YsB  = YsA + 8 * 384;
    float*  Xall = YsB + 8 * 384;                 // 67*16 floats

    int tid = threadIdx.x;
    int c   = blockIdx.y;
    int a0  = blockIdx.x * 16;
    int wrp = tid >> 5, l = tid & 31;

    int t0c = c * LC;
    int t1c = t0c + LC; if (t1c > TT) t1c = TT;
    int nb  = (t1c - t0c + 7) >> 3;   // always 4

    // scan mapping: 4 a x 2 d (R5)
    int d2 = tid & 63;
    int ag = tid >> 6;

    // gemm mapping
    int grp = l >> 2, thr = l & 3;
    int mg  = wrp & 3, ng = wrp >> 2;
    int h0  = mg * 32;

    // prologue: prefetch Y(0); stage Xall
    {
        int nvt0 = t1c - t0c; if (nvt0 > 8) nvt0 = 8;
        uint32_t ydst = smem_u32(YsA);
        const float* ysrc = g_Y + t0c * 384;
        for (int i = tid; i < nvt0 * 96; i += 256)
            asm volatile("cp.async.ca.shared.global [%0], [%1], 16;"
                         :: "r"(ydst + i * 16), "l"(ysrc + i * 4));
        asm volatile("cp.async.commit_group;");
    }
    for (int i = tid; i < 67 * 16; i += 256) {
        int r = i >> 4, al = i & 15;
        int row = 2 * t0c + r;
        Xall[i] = (row < 8192) ? in[(size_t)row * H + a0 + al] : 0.0f;
    }

    // A fragments: C rows [h0,h0+32), fp16. 8 k-tiles x 8 half2 regs.
    uint32_t afr[8][8];
#pragma unroll
    for (int kt = 0; kt < 8; kt++) {
        int cb = kt * 16 + 2 * thr;
#pragma unroll
        for (int mt = 0; mt < 2; mt++) {
            const float* r0 = Cm + (h0 + mt * 16 + grp) * H;
            const float* r1 = Cm + (h0 + mt * 16 + grp + 8) * H;
            __half2 p0 = __floats2half2_rn(r0[cb],     r0[cb + 1]);
            __half2 p1 = __floats2half2_rn(r1[cb],     r1[cb + 1]);
            __half2 p2 = __floats2half2_rn(r0[cb + 8], r0[cb + 9]);
            __half2 p3 = __floats2half2_rn(r1[cb + 8], r1[cb + 9]);
            afr[kt][mt * 4 + 0] = *(uint32_t*)&p0;
            afr[kt][mt * 4 + 1] = *(uint32_t*)&p1;
            afr[kt][mt * 4 + 2] = *(uint32_t*)&p2;
            afr[kt][mt * 4 + 3] = *(uint32_t*)&p3;
        }
    }

    // scan state: 4 a x 2 d per thread
    float z[8], lam[8];
#pragma unroll
    for (int j = 0; j < 4; j++) {
        int a = a0 + ag * 4 + j;
        float2 lv = *(const float2*)&Lam[a * H + 2 * d2];
        float2 cv = *(const float2*)&g_cin[c * NELEM + a * H + 2 * d2];
        lam[j * 2]     = lv.x;  lam[j * 2 + 1] = lv.y;
        z[j * 2]       = cv.x;  z[j * 2 + 1]   = cv.y;
    }

    for (int e = 0; e <= nb; e++) {
        asm volatile("cp.async.wait_group 0;");
        __syncthreads();

        if (e < nb) {
            // prefetch Y(e+1) (lands during this epoch's gemm)
            if (e + 1 < nb) {
                int tb1  = t0c + (e + 1) * 8;
                int nvt1 = t1c - tb1; if (nvt1 > 8) nvt1 = 8;
                uint32_t ydst = smem_u32((e + 1) & 1 ? YsB : YsA);
                const float* ysrc = g_Y + tb1 * 384;
                for (int i = tid; i < nvt1 * 96; i += 256)
                    asm volatile("cp.async.ca.shared.global [%0], [%1], 16;"
                                 :: "r"(ydst + i * 16), "l"(ysrc + i * 4));
                asm volatile("cp.async.commit_group;");
            }

            // ---- scan epoch e -> Zs[e&1] ----
            int tb  = t0c + e * 8;
            int nvt = t1c - tb; if (nvt > 8) nvt = 8;
            const float* Yb = (e & 1) ? YsB : YsA;
            __half* Zb = (e & 1) ? ZsB : ZsA;
            for (int tl = 0; tl < nvt; tl++) {
                float2 y0 = *(const float2*)&Yb[tl * 384 + 2 * d2];
                float2 y1 = *(const float2*)&Yb[tl * 384 + 128 + 2 * d2];
                float2 y2 = *(const float2*)&Yb[tl * 384 + 256 + 2 * d2];
                int dt = 2 * (tb - t0c + tl);
                const float* xs = &Xall[dt * 16 + ag * 4];
#pragma unroll
                for (int j = 0; j < 4; j++) {
                    float xa0 = xs[j], xa1 = xs[16 + j], xa2 = xs[32 + j];
                    float u0 = xa0 * y0.x + xa1 * y1.x + xa2 * y2.x;
                    float u1 = xa0 * y0.y + xa1 * y1.y + xa2 * y2.y;
                    z[j * 2]     = fmaf(lam[j * 2],     z[j * 2],     u0);
                    z[j * 2 + 1] = fmaf(lam[j * 2 + 1], z[j * 2 + 1], u1);
                    *(__half2*)&Zb[(tl * 16 + ag * 4 + j) * ZSH + 2 * d2] =
                        __floats2half2_rn(z[j * 2], z[j * 2 + 1]);
                }
            }
        }

        // ---- gemm epoch e-1 <- Zs[(e-1)&1] ----
        if (e > 0) {
            int jb = e - 1;
            int tb = t0c + jb * 8;
            const __half* Zb = (jb & 1) ? ZsB : ZsA;
            for (int nt = ng * 8; nt < ng * 8 + 8; nt++) {
                int t = tb + (nt >> 1);
                if (t >= TT) break;
                float acc[8];
#pragma unroll
                for (int i = 0; i < 8; i++) acc[i] = 0.0f;
                const __half* zb = Zb + (nt * 8 + grp) * ZSH + 2 * thr;
#pragma unroll
                for (int kt = 0; kt < 8; kt++) {
                    uint32_t b0 = *(const uint32_t*)(zb + kt * 16);
                    uint32_t b1 = *(const uint32_t*)(zb + kt * 16 + 8);
                    asm volatile(
                        "mma.sync.aligned.m16n8k16.row.col.f32.f16.f16.f32 "
                        "{%0,%1,%2,%3}, {%4,%5,%6,%7}, {%8,%9}, {%0,%1,%2,%3};"
                        : "+f"(acc[0]), "+f"(acc[1]), "+f"(acc[2]), "+f"(acc[3])
                        : "r"(afr[kt][0]), "r"(afr[kt][1]), "r"(afr[kt][2]),
                          "r"(afr[kt][3]), "r"(b0), "r"(b1));
                    asm volatile(
                        "mma.sync.aligned.m16n8k16.row.col.f32.f16.f16.f32 "
                        "{%0,%1,%2,%3}, {%4,%5,%6,%7}, {%8,%9}, {%0,%1,%2,%3};"
                        : "+f"(acc[4]), "+f"(acc[5]), "+f"(acc[6]), "+f"(acc[7])
                        : "r"(afr[kt][4]), "r"(afr[kt][5]), "r"(afr[kt][6]),
                          "r"(afr[kt][7]), "r"(b0), "r"(b1));
                }
                float* ob = out + (size_t)t * NELEM + a0 + (nt & 1) * 8 + 2 * thr;
                asm volatile("st.global.cs.v2.f32 [%0], {%1,%2};"
                             :: "l"(ob + (size_t)(h0 + grp) * H),
                                "f"(acc[0]), "f"(acc[1]));
                asm volatile("st.global.cs.v2.f32 [%0], {%1,%2};"
                             :: "l"(ob + (size_t)(h0 + grp + 8) * H),
                                "f"(acc[2]), "f"(acc[3]));
                asm volatile("st.global.cs.v2.f32 [%0], {%1,%2};"
                             :: "l"(ob + (size_t)(h0 + 16 + grp) * H),
                                "f"(acc[4]), "f"(acc[5]));
                asm volatile("st.global.cs.v2.f32 [%0], {%1,%2};"
                             :: "l"(ob + (size_t)(h0 + 24 + grp) * H),
                                "f"(acc[6]), "f"(acc[7]));
            }
        }
    }
}

// ---------------------------------------------------------------------------
// Launch: prep -> scan0 -> combine -> fused(scan+GEMM)
// Output layout: zs_out (T*H*H floats) followed by os (T*H floats).
// ---------------------------------------------------------------------------
extern "C" void kernel_launch(void* const* d_in, const int* in_sizes, int n_in,
                              void* d_out, int out_size) {
    const float* in  = (const float*)d_in[0];   // input_sequence (8192,128)
    const float* lam = (const float*)d_in[1];   // Lambda_bar (128,128)
    const float* Cm  = (const float*)d_in[2];   // C_tilde (128,128)
    const float* wq  = (const float*)d_in[3];   // w_q (3,3)
    const float* Dv  = (const float*)d_in[4];   // D (3,)
    (void)in_sizes; (void)n_in; (void)out_size;

    float* out    = (float*)d_out;
    float* os_out = out + (size_t)TT * NELEM;

    // smem: 2x Zs (halves) + 2x Ys + Xall
    const int fused_smem = 2 * 128 * ZSH * (int)sizeof(__half)
                         + 2 * 8 * 384 * (int)sizeof(float)
                         + 67 * 16 * (int)sizeof(float);
    cudaFuncSetAttribute(fused_kernel, cudaFuncAttributeMaxDynamicSharedMemorySize,
                         fused_smem);

    prep_kernel<<<TT, H>>>(in, wq, Dv, os_out);
    scan0_kernel<<<dim3(8, NC), 256>>>(in, lam);
    combine_kernel<<<NELEM / 256, 256>>>(lam);
    fused_kernel<<<dim3(8, NC), 256, fused_smem>>>(in, lam, Cm, out);
}